// round 13
// baseline (speedup 1.0000x reference)
#include <cuda_runtime.h>
#include <cstdint>

#define BB 16
#define AA 8400
#define GG 64
#define CC 80
#define KK 10
#define NC 20            // cells per dimension (32px cells over 640px)
#define NCELL (NC * NC)
#define CAP 640          // candidate list cap per (b,g); max observed ~420
#define FB 60            // anchors per fill block (8400 = 140 * 60)
#define FT 240           // fill threads per block
#define FEPS 1e-9f

// Scratch (allocation-free rule: __device__ globals; zero-initialized at load).
// g_key/g_normb are zeroed at the START of each call (cellbin) before select
// writes them; fill only reads. g_cnt reset by select; g_cg* rebuilt per call.
__device__ unsigned long long g_key[BB * AA];    // packed (ciou_bits<<32)|(G-1-g)
__device__ unsigned int       g_normb[BB * AA];  // float bits of norm
__device__ int                g_cnt[BB * GG];    // candidate counts
__device__ unsigned long long g_ckey[BB * GG * CAP];  // (align_bits<<32)|(AA-a)
__device__ unsigned char      g_cgidx[BB * NCELL * GG];  // gt ids per (b,cell)
__device__ int                g_cgcnt[BB * NCELL];

// ---------------------------------------------------------------------------
// CIoU, mirroring reference op order; at1/at2 precomputed
// ---------------------------------------------------------------------------
__device__ __forceinline__ float ciou_fn(
    float gx1, float gy1, float gx2, float gy2,
    float area1, float at1,
    float dx1, float dy1, float dx2, float dy2,
    float w2, float h2, float at2)
{
    float xx1 = fmaxf(gx1, dx1), yy1 = fmaxf(gy1, dy1);
    float xx2 = fminf(gx2, dx2), yy2 = fminf(gy2, dy2);
    float iw = fmaxf(xx2 - xx1, 0.0f), ih = fmaxf(yy2 - yy1, 0.0f);
    float inter = iw * ih;
    float uni = area1 + w2 * h2 - inter;
    float iou = __fdiv_rn(inter, uni + FEPS);
    float cw = fmaxf(gx2, dx2) - fminf(gx1, dx1);
    float ch = fmaxf(gy2, dy2) - fminf(gy1, dy1);
    float c2 = cw * cw + ch * ch + FEPS;
    float ex = (gx1 + gx2) - (dx1 + dx2);
    float ey = (gy1 + gy2) - (dy1 + dy2);
    float rho2 = (ex * ex + ey * ey) * 0.25f;
    float dat = at1 - at2;
    float v = 0.40528473456935108577f * dat * dat;  // 4/pi^2
    float al = __fdiv_rn(v, v - iou + 1.0f + FEPS);
    return iou - (__fdiv_rn(rho2, c2) + v * al);
}

// ---------------------------------------------------------------------------
// cellbin: one WARP per (b,cell) — 6400 warps, 800 blocks. Two ballot rounds
// over the 64 gts; popc-compacted list writes. Also zeroes g_key/g_normb.
// ---------------------------------------------------------------------------
__global__ __launch_bounds__(256) void cellbin_kernel(
    const float* __restrict__ gt_bboxes, const unsigned char* __restrict__ mask_raw)
{
    int tid = threadIdx.x;

    // zero argmax scratch: 204800 threads cover BB*AA = 134400
    int zt = blockIdx.x * 256 + tid;
    if (zt < BB * AA) { g_key[zt] = 0ull; g_normb[zt] = 0u; }

    // mask dtype detection over first BB*GG bytes (in-bounds for all dtypes)
    unsigned int mword = ((const unsigned int*)mask_raw)[tid];
    int myflags = 0;
    if (((mword >> 24) & 0xFF) == 0x3F) myflags |= 1;   // f32
    if (((mword >> 8)  & 0xFF) == 0x3F) myflags |= 2;   // bf16
    if ((mword & 0xFFFFFF00u) != 0)     myflags |= 4;   // u8 packed
    int allflags = __syncthreads_or(myflags);
    int mode = (allflags & 2) ? 3 : ((allflags & 1) ? 2 : ((allflags & 4) ? 0 : 1));

    int warp = blockIdx.x * 8 + (tid >> 5);  // 800*8 = 6400 = BB*NCELL exactly
    int lane = tid & 31;
    int b = warp / NCELL, cell = warp % NCELL;
    float clx = (float)(cell % NC) * 32.0f, cly = (float)(cell / NC) * 32.0f;
    float chx = clx + 32.0f, chy = cly + 32.0f;

    int base = 0;
#pragma unroll
    for (int half = 0; half < 2; half++) {
        int g = half * 32 + lane;
        int bg = b * GG + g;
        int mk;
        if (mode == 0)      mk = (mask_raw[bg] != 0);
        else if (mode == 3) mk = (((const unsigned short*)mask_raw)[bg] != 0);
        else                mk = (((const unsigned int*)mask_raw)[bg] != 0);
        float4 gb = __ldg(((const float4*)gt_bboxes) + bg);
        bool pass = mk && gb.x < chx && gb.z > clx && gb.y < chy && gb.w > cly;
        unsigned int bal = __ballot_sync(0xffffffffu, pass);
        if (pass) {
            int pos = base + __popc(bal & ((1u << lane) - 1));
            g_cgidx[warp * GG + pos] = (unsigned char)g;
        }
        base += __popc(bal);
    }
    if (lane == 0) g_cgcnt[warp] = base;
}

// ---------------------------------------------------------------------------
// scan: thread per (b,anchor), coalesced anchor/dbox loads. Inner loop only
// over the ~1.3 gts listed for this anchor's cell.
// ---------------------------------------------------------------------------
__global__ __launch_bounds__(256) void scan_kernel(
    const float* __restrict__ scores, const float* __restrict__ dbox,
    const float* __restrict__ anchors, const int* __restrict__ gt_labels,
    const float* __restrict__ gt_bboxes)
{
    int b = blockIdx.y;
    int a = blockIdx.x * 256 + threadIdx.x;
    if (a >= AA) return;

    float2 an = ((const float2*)anchors)[a];
    int cx = (int)floorf(an.x * (1.0f / 32.0f));
    int cy = (int)floorf(an.y * (1.0f / 32.0f));
    cx = cx < 0 ? 0 : (cx > NC - 1 ? NC - 1 : cx);
    cy = cy < 0 ? 0 : (cy > NC - 1 ? NC - 1 : cy);
    int t = b * NCELL + cy * NC + cx;

    int cnt = g_cgcnt[t];
    if (cnt == 0) return;

    float4 d = ((const float4*)dbox)[(size_t)b * AA + a];
    float w2 = d.z - d.x, h2 = d.w - d.y;
    float at2 = atanf(__fdiv_rn(w2, h2 + FEPS));
    const float* srow = scores + ((size_t)b * AA + a) * CC;
    const unsigned char* glist = g_cgidx + (size_t)t * GG;

    for (int j = 0; j < cnt; j++) {
        int g = glist[j];
        int bg = b * GG + g;
        float4 gb = __ldg(((const float4*)gt_bboxes) + bg);
        if (!(gb.x < an.x && gb.y < an.y && gb.z > an.x && gb.w > an.y))
            continue;
        float w1 = gb.z - gb.x, h1 = gb.w - gb.y;
        float at1 = atanf(__fdiv_rn(w1, h1 + FEPS));
        float ov = ciou_fn(gb.x, gb.y, gb.z, gb.w, w1 * h1, at1,
                           d.x, d.y, d.z, d.w, w2, h2, at2);
        if (ov <= 0.0f) continue;
        int lab = __ldg(&gt_labels[bg]);
        if (lab < 0) lab = 0;
        float s = __ldg(srow + lab);
        float p2 = ov * ov;
        float align = sqrtf(s) * (p2 * p2 * p2);
        if (align <= 0.0f) continue;
        int pos = atomicAdd(&g_cnt[bg], 1);
        if (pos < CAP) {
            g_ckey[(size_t)bg * CAP + pos] =
                ((unsigned long long)__float_as_uint(align) << 32) |
                (unsigned int)(AA - a);  // smaller a -> larger key (ties)
        }
    }
}

// ---------------------------------------------------------------------------
// select: one warp per (b,g), 64-thread blocks (512 blocks resident).
// Top-10 over candidate list; per-anchor argmax/norm atomics; resets g_cnt.
// ---------------------------------------------------------------------------
__global__ __launch_bounds__(64) void select_kernel(
    const float* __restrict__ dbox, const float* __restrict__ gt_bboxes)
{
    int bg = blockIdx.x * 2 + (threadIdx.x >> 5);
    int lane = threadIdx.x & 31;

    int n = g_cnt[bg];
    if (lane == 0) g_cnt[bg] = 0;
    if (n > CAP) n = CAP;
    if (n == 0) return;

    int b = bg >> 6, g = bg & 63;

    // per-lane sorted top-10
    unsigned long long kk[KK];
#pragma unroll
    for (int j = 0; j < KK; j++) kk[j] = 0ull;
    const unsigned long long* ck = g_ckey + (size_t)bg * CAP;
    for (int i = lane; i < n; i += 32) {
        unsigned long long key = ck[i];
        if (key > kk[KK - 1]) {
            kk[KK - 1] = key;
#pragma unroll
            for (int j = KK - 2; j >= 0; j--) {
                unsigned long long x = kk[j], y = kk[j + 1];
                kk[j]     = x > y ? x : y;
                kk[j + 1] = x > y ? y : x;
            }
        }
    }

    // warp-wide strict-descending selection of top-10 (lane k holds round k)
    unsigned long long last = ~0ull;
    unsigned long long wkey = 0ull;
    for (int k = 0; k < KK; k++) {
        unsigned long long cand = 0ull;
#pragma unroll
        for (int j = 0; j < KK; j++) {
            unsigned long long v = kk[j];
            if (v < last && v > cand) cand = v;
        }
#pragma unroll
        for (int o = 16; o; o >>= 1) {
            unsigned long long t = __shfl_xor_sync(0xffffffffu, cand, o);
            if (t > cand) cand = t;
        }
        if (lane == k) wkey = cand;
        last = cand;
        if (cand == 0ull) break;
    }

    // recompute ciou for winners (<=10), reduce max_ovl, emit atomics
    float my_ciou = 0.0f, my_align = 0.0f;
    int my_a = -1;
    if (lane < KK && wkey != 0ull) {
        my_a = AA - (int)(unsigned int)(wkey & 0xffffffffull);
        my_align = __uint_as_float((unsigned int)(wkey >> 32));
        float4 gb = __ldg(((const float4*)gt_bboxes) + bg);
        float w1 = gb.z - gb.x, h1 = gb.w - gb.y;
        float at1 = atanf(__fdiv_rn(w1, h1 + FEPS));
        float4 d = ((const float4*)dbox)[(size_t)b * AA + my_a];
        float w2 = d.z - d.x, h2 = d.w - d.y;
        float at2 = atanf(__fdiv_rn(w2, h2 + FEPS));
        my_ciou = ciou_fn(gb.x, gb.y, gb.z, gb.w, w1 * h1, at1,
                          d.x, d.y, d.z, d.w, w2, h2, at2);
    }
    float max_ovl = my_ciou;
#pragma unroll
    for (int o = 16; o; o >>= 1)
        max_ovl = fmaxf(max_ovl, __shfl_xor_sync(0xffffffffu, max_ovl, o));

    unsigned long long w0 = __shfl_sync(0xffffffffu, wkey, 0);
    float max_align = __uint_as_float((unsigned int)(w0 >> 32));

    if (my_a >= 0) {
        float normv = __fdiv_rn(my_align * max_ovl, max_align + FEPS);
        unsigned long long akey =
            ((unsigned long long)__float_as_uint(my_ciou) << 32) |
            (unsigned int)(GG - 1 - g);  // smaller g wins ties
        atomicMax(&g_key[(size_t)b * AA + my_a], akey);
        atomicMax(&g_normb[(size_t)b * AA + my_a], __float_as_uint(normv));
    }
}

// ---------------------------------------------------------------------------
// fill: one block per 60 anchors, 240 threads, 2D grid (140, B) = 2240 blocks,
// ~22KB smem (full-carveout attr => ~8 blocks/SM, thread-limited). Threads<64
// prefetch the batch gt tables; threads<60 resolve their anchor from smem;
// all 240 zero the class tile (5 STS.128 each). 4 cp.async.bulk ops move the
// staged tile (sizes/addresses all 16B-multiples); tid0 waits to keep smem
// alive, other threads retire. READ-ONLY on scratch.
// Output layout: bbox[B,A,4] | cls_oh[B,A,C] | dist[B,A,1] | fg[B,A]
// ---------------------------------------------------------------------------
__global__ __launch_bounds__(FT) void fill_kernel(
    const int* __restrict__ gt_labels, const float* __restrict__ gt_bboxes,
    const float* __restrict__ gt_dist, float* __restrict__ out)
{
    __shared__ __align__(16) float  s_cls[FB * CC];   // 19200 B
    __shared__ __align__(16) float4 s_bbox[FB];       // 960 B
    __shared__ __align__(16) float  s_dist[FB];       // 240 B
    __shared__ __align__(16) float  s_fg[FB];         // 240 B
    __shared__ float4 s_gbox[GG];                     // 1024 B
    __shared__ float  s_gdist[GG];                    // 256 B
    __shared__ int    s_glab[GG];                     // 256 B

    int tid = threadIdx.x;
    int b = blockIdx.y;
    int w0 = b * AA + blockIdx.x * FB;

    // independent load streams: key/normb (anchors), gt tables, zero-fill
    unsigned long long key = 0ull;
    unsigned int normb = 0u;
    if (tid < FB) {
        key = __ldg(&g_key[w0 + tid]);
        normb = __ldg(&g_normb[w0 + tid]);
    }
    if (tid < GG) {
        int bg = b * GG + tid;
        s_gbox[tid]  = __ldg(((const float4*)gt_bboxes) + bg);
        s_gdist[tid] = __ldg(&gt_dist[bg]);
        s_glab[tid]  = __ldg(&gt_labels[bg]);
    }
    float4* s4 = (float4*)s_cls;
    float4 z = make_float4(0.f, 0.f, 0.f, 0.f);
#pragma unroll
    for (int r = 0; r < (FB * CC / 4) / FT; r++)   // 1200/240 = 5 STS.128 each
        s4[r * FT + tid] = z;
    __syncthreads();

    // resolve from smem tables (no dependent global gather)
    if (tid < FB) {
        float norm = __uint_as_float(normb);
        bool matched = (key != 0ull);
        int gm = (GG - 1) - ((int)key & (GG - 1));
        int label = matched ? s_glab[gm] : -1;
        s_bbox[tid] = matched ? s_gbox[gm] : make_float4(-1.f, -1.f, -1.f, -1.f);
        s_dist[tid] = (matched ? s_gdist[gm] : -1.0f) * norm;
        s_fg[tid] = 1.0f;   // argmax >= 0 always
        if (label >= 0)
            s_cls[tid * CC + label] = norm;
    }
    __syncthreads();

    if (tid == 0) {
        asm volatile("fence.proxy.async.shared::cta;" ::: "memory");
        uint32_t sa;
        float* out_cls  = out + (size_t)BB * AA * 4 + (size_t)w0 * CC;
        float* out_bbox = out + (size_t)w0 * 4;
        float* out_dist = out + (size_t)BB * AA * (4 + CC) + w0;
        float* out_fg   = out + (size_t)BB * AA * (5 + CC) + w0;

        asm("{ .reg .u64 t; cvta.to.shared.u64 t, %1; cvt.u32.u64 %0, t; }"
            : "=r"(sa) : "l"((void*)s_cls));
        asm volatile("cp.async.bulk.global.shared::cta.bulk_group [%0], [%1], %2;"
                     :: "l"(out_cls), "r"(sa), "r"((unsigned)(FB * CC * 4)) : "memory");
        asm("{ .reg .u64 t; cvta.to.shared.u64 t, %1; cvt.u32.u64 %0, t; }"
            : "=r"(sa) : "l"((void*)s_bbox));
        asm volatile("cp.async.bulk.global.shared::cta.bulk_group [%0], [%1], %2;"
                     :: "l"(out_bbox), "r"(sa), "r"((unsigned)(FB * 16)) : "memory");
        asm("{ .reg .u64 t; cvta.to.shared.u64 t, %1; cvt.u32.u64 %0, t; }"
            : "=r"(sa) : "l"((void*)s_dist));
        asm volatile("cp.async.bulk.global.shared::cta.bulk_group [%0], [%1], %2;"
                     :: "l"(out_dist), "r"(sa), "r"((unsigned)(FB * 4)) : "memory");
        asm("{ .reg .u64 t; cvta.to.shared.u64 t, %1; cvt.u32.u64 %0, t; }"
            : "=r"(sa) : "l"((void*)s_fg));
        asm volatile("cp.async.bulk.global.shared::cta.bulk_group [%0], [%1], %2;"
                     :: "l"(out_fg), "r"(sa), "r"((unsigned)(FB * 4)) : "memory");
        asm volatile("cp.async.bulk.commit_group;" ::: "memory");
        asm volatile("cp.async.bulk.wait_group 0;" ::: "memory");
    }
}

// ---------------------------------------------------------------------------
extern "C" void kernel_launch(void* const* d_in, const int* in_sizes, int n_in,
                              void* d_out, int out_size) {
    const float* scores = nullptr;
    const float* dbox = nullptr;
    const float* anchors = nullptr;
    const float* gtb = nullptr;
    const int* gtl = nullptr;
    const float* gtd = nullptr;
    const unsigned char* gmask = nullptr;
    int small_seen = 0;
    for (int i = 0; i < n_in; i++) {
        int s = in_sizes[i];
        if (s == BB * AA * CC)      scores = (const float*)d_in[i];
        else if (s == BB * AA * 4)  dbox = (const float*)d_in[i];
        else if (s == AA * 2)       anchors = (const float*)d_in[i];
        else if (s == BB * GG * 4)  gtb = (const float*)d_in[i];
        else if (s == BB * GG) {
            if (small_seen == 0)      gtl = (const int*)d_in[i];
            else if (small_seen == 1) gtd = (const float*)d_in[i];
            else                      gmask = (const unsigned char*)d_in[i];
            small_seen++;
        }
    }

    // request full smem carveout so ~8 fill blocks fit per SM (idempotent)
    cudaFuncSetAttribute(fill_kernel,
                         cudaFuncAttributePreferredSharedMemoryCarveout, 100);

    cellbin_kernel<<<BB * NCELL / 8, 256>>>(gtb, gmask);
    scan_kernel<<<dim3((AA + 255) / 256, BB), 256>>>(scores, dbox, anchors, gtl, gtb);
    select_kernel<<<BB * GG / 2, 64>>>(dbox, gtb);
    fill_kernel<<<dim3(AA / FB, BB), FT>>>(gtl, gtb, gtd, (float*)d_out);
}

// round 15
// speedup vs baseline: 1.0031x; 1.0031x over previous
#include <cuda_runtime.h>
#include <cstdint>

#define BB 16
#define AA 8400
#define GG 64
#define CC 80
#define KK 10
#define NC 20            // cells per dimension (32px cells over 640px)
#define NCELL (NC * NC)
#define CAP 640          // candidate list cap per (b,g); max observed ~420
#define FEPS 1e-9f

// Scratch (allocation-free rule: __device__ globals; zero-initialized at load).
// g_key/g_normb are zeroed at the START of each call (cellbin) before select
// writes them; fill only reads. g_cnt reset by select; g_cg* rebuilt per call.
__device__ unsigned long long g_key[BB * AA];    // packed (ciou_bits<<32)|(G-1-g)
__device__ unsigned int       g_normb[BB * AA];  // float bits of norm
__device__ int                g_cnt[BB * GG];    // candidate counts
__device__ unsigned long long g_ckey[BB * GG * CAP];  // (align_bits<<32)|(AA-a)
__device__ unsigned char      g_cgidx[BB * NCELL * GG];  // gt ids per (b,cell)
__device__ int                g_cgcnt[BB * NCELL];

// ---------------------------------------------------------------------------
// CIoU, mirroring reference op order; at1/at2 precomputed
// ---------------------------------------------------------------------------
__device__ __forceinline__ float ciou_fn(
    float gx1, float gy1, float gx2, float gy2,
    float area1, float at1,
    float dx1, float dy1, float dx2, float dy2,
    float w2, float h2, float at2)
{
    float xx1 = fmaxf(gx1, dx1), yy1 = fmaxf(gy1, dy1);
    float xx2 = fminf(gx2, dx2), yy2 = fminf(gy2, dy2);
    float iw = fmaxf(xx2 - xx1, 0.0f), ih = fmaxf(yy2 - yy1, 0.0f);
    float inter = iw * ih;
    float uni = area1 + w2 * h2 - inter;
    float iou = __fdiv_rn(inter, uni + FEPS);
    float cw = fmaxf(gx2, dx2) - fminf(gx1, dx1);
    float ch = fmaxf(gy2, dy2) - fminf(gy1, dy1);
    float c2 = cw * cw + ch * ch + FEPS;
    float ex = (gx1 + gx2) - (dx1 + dx2);
    float ey = (gy1 + gy2) - (dy1 + dy2);
    float rho2 = (ex * ex + ey * ey) * 0.25f;
    float dat = at1 - at2;
    float v = 0.40528473456935108577f * dat * dat;  // 4/pi^2
    float al = __fdiv_rn(v, v - iou + 1.0f + FEPS);
    return iou - (__fdiv_rn(rho2, c2) + v * al);
}

// ---------------------------------------------------------------------------
// cellbin: one WARP per (b,cell) — 6400 warps, 800 blocks. Two ballot rounds
// over the 64 gts; popc-compacted list writes. Also zeroes g_key/g_normb.
// ---------------------------------------------------------------------------
__global__ __launch_bounds__(256) void cellbin_kernel(
    const float* __restrict__ gt_bboxes, const unsigned char* __restrict__ mask_raw)
{
    int tid = threadIdx.x;

    // zero argmax scratch: 204800 threads cover BB*AA = 134400
    int zt = blockIdx.x * 256 + tid;
    if (zt < BB * AA) { g_key[zt] = 0ull; g_normb[zt] = 0u; }

    // mask dtype detection over first BB*GG bytes (in-bounds for all dtypes)
    unsigned int mword = ((const unsigned int*)mask_raw)[tid];
    int myflags = 0;
    if (((mword >> 24) & 0xFF) == 0x3F) myflags |= 1;   // f32
    if (((mword >> 8)  & 0xFF) == 0x3F) myflags |= 2;   // bf16
    if ((mword & 0xFFFFFF00u) != 0)     myflags |= 4;   // u8 packed
    int allflags = __syncthreads_or(myflags);
    int mode = (allflags & 2) ? 3 : ((allflags & 1) ? 2 : ((allflags & 4) ? 0 : 1));

    int warp = blockIdx.x * 8 + (tid >> 5);  // 800*8 = 6400 = BB*NCELL exactly
    int lane = tid & 31;
    int b = warp / NCELL, cell = warp % NCELL;
    float clx = (float)(cell % NC) * 32.0f, cly = (float)(cell / NC) * 32.0f;
    float chx = clx + 32.0f, chy = cly + 32.0f;

    int base = 0;
#pragma unroll
    for (int half = 0; half < 2; half++) {
        int g = half * 32 + lane;
        int bg = b * GG + g;
        int mk;
        if (mode == 0)      mk = (mask_raw[bg] != 0);
        else if (mode == 3) mk = (((const unsigned short*)mask_raw)[bg] != 0);
        else                mk = (((const unsigned int*)mask_raw)[bg] != 0);
        float4 gb = __ldg(((const float4*)gt_bboxes) + bg);
        bool pass = mk && gb.x < chx && gb.z > clx && gb.y < chy && gb.w > cly;
        unsigned int bal = __ballot_sync(0xffffffffu, pass);
        if (pass) {
            int pos = base + __popc(bal & ((1u << lane) - 1));
            g_cgidx[warp * GG + pos] = (unsigned char)g;
        }
        base += __popc(bal);
    }
    if (lane == 0) g_cgcnt[warp] = base;
}

// ---------------------------------------------------------------------------
// scan: thread per (b,anchor). FIRST issues the data-independent output
// stores (cls one-hot zero region, <=20 STG.128/thread, + fg=1.0) so the
// store wall drains concurrently with the candidate compute below.
// Then: coalesced anchor/dbox loads, inner loop over the ~1.3 gts listed
// for this anchor's cell, candidates pushed to per-(b,g) lists.
// Output layout: bbox[B,A,4] | cls_oh[B,A,C] | dist[B,A,1] | fg[B,A]
// ---------------------------------------------------------------------------
__global__ __launch_bounds__(256) void scan_kernel(
    const float* __restrict__ scores, const float* __restrict__ dbox,
    const float* __restrict__ anchors, const int* __restrict__ gt_labels,
    const float* __restrict__ gt_bboxes, float* __restrict__ out)
{
    int b = blockIdx.y;
    int tid = threadIdx.x;
    int a = blockIdx.x * 256 + tid;

    // ---- fused output stores (independent; fire-and-forget) ----
    {
        float4* out_cls4 = (float4*)(out + (size_t)BB * AA * 4);
        int a0 = blockIdx.x * 256;
        int nanch = AA - a0; if (nanch > 256) nanch = 256;
        size_t qbase = ((size_t)b * AA + a0) * (CC / 4);
        int nq = nanch * (CC / 4);                  // <= 5120
        float4 z = make_float4(0.f, 0.f, 0.f, 0.f);
        for (int r = tid; r < nq; r += 256)         // <= 20 STG.128
            out_cls4[qbase + r] = z;
        if (a < AA) {
            float* out_fg = out + (size_t)BB * AA * (5 + CC);
            out_fg[b * AA + a] = 1.0f;              // argmax >= 0 always
        }
    }

    if (a >= AA) return;

    float2 an = ((const float2*)anchors)[a];
    int cx = (int)floorf(an.x * (1.0f / 32.0f));
    int cy = (int)floorf(an.y * (1.0f / 32.0f));
    cx = cx < 0 ? 0 : (cx > NC - 1 ? NC - 1 : cx);
    cy = cy < 0 ? 0 : (cy > NC - 1 ? NC - 1 : cy);
    int t = b * NCELL + cy * NC + cx;

    int cnt = g_cgcnt[t];
    if (cnt == 0) return;

    float4 d = ((const float4*)dbox)[(size_t)b * AA + a];
    float w2 = d.z - d.x, h2 = d.w - d.y;
    float at2 = atanf(__fdiv_rn(w2, h2 + FEPS));
    const float* srow = scores + ((size_t)b * AA + a) * CC;
    const unsigned char* glist = g_cgidx + (size_t)t * GG;

    for (int j = 0; j < cnt; j++) {
        int g = glist[j];
        int bg = b * GG + g;
        float4 gb = __ldg(((const float4*)gt_bboxes) + bg);
        if (!(gb.x < an.x && gb.y < an.y && gb.z > an.x && gb.w > an.y))
            continue;
        float w1 = gb.z - gb.x, h1 = gb.w - gb.y;
        float at1 = atanf(__fdiv_rn(w1, h1 + FEPS));
        float ov = ciou_fn(gb.x, gb.y, gb.z, gb.w, w1 * h1, at1,
                           d.x, d.y, d.z, d.w, w2, h2, at2);
        if (ov <= 0.0f) continue;
        int lab = __ldg(&gt_labels[bg]);
        if (lab < 0) lab = 0;
        float s = __ldg(srow + lab);
        float p2 = ov * ov;
        float align = sqrtf(s) * (p2 * p2 * p2);
        if (align <= 0.0f) continue;
        int pos = atomicAdd(&g_cnt[bg], 1);
        if (pos < CAP) {
            g_ckey[(size_t)bg * CAP + pos] =
                ((unsigned long long)__float_as_uint(align) << 32) |
                (unsigned int)(AA - a);  // smaller a -> larger key (ties)
        }
    }
}

// ---------------------------------------------------------------------------
// select: one warp per (b,g), 64-thread blocks (512 blocks resident).
// Top-10 over candidate list; per-anchor argmax/norm atomics; resets g_cnt.
// ---------------------------------------------------------------------------
__global__ __launch_bounds__(64) void select_kernel(
    const float* __restrict__ dbox, const float* __restrict__ gt_bboxes)
{
    int bg = blockIdx.x * 2 + (threadIdx.x >> 5);
    int lane = threadIdx.x & 31;

    int n = g_cnt[bg];
    if (lane == 0) g_cnt[bg] = 0;
    if (n > CAP) n = CAP;
    if (n == 0) return;

    int b = bg >> 6, g = bg & 63;

    // per-lane sorted top-10
    unsigned long long kk[KK];
#pragma unroll
    for (int j = 0; j < KK; j++) kk[j] = 0ull;
    const unsigned long long* ck = g_ckey + (size_t)bg * CAP;
    for (int i = lane; i < n; i += 32) {
        unsigned long long key = ck[i];
        if (key > kk[KK - 1]) {
            kk[KK - 1] = key;
#pragma unroll
            for (int j = KK - 2; j >= 0; j--) {
                unsigned long long x = kk[j], y = kk[j + 1];
                kk[j]     = x > y ? x : y;
                kk[j + 1] = x > y ? y : x;
            }
        }
    }

    // warp-wide strict-descending selection of top-10 (lane k holds round k)
    unsigned long long last = ~0ull;
    unsigned long long wkey = 0ull;
    for (int k = 0; k < KK; k++) {
        unsigned long long cand = 0ull;
#pragma unroll
        for (int j = 0; j < KK; j++) {
            unsigned long long v = kk[j];
            if (v < last && v > cand) cand = v;
        }
#pragma unroll
        for (int o = 16; o; o >>= 1) {
            unsigned long long t = __shfl_xor_sync(0xffffffffu, cand, o);
            if (t > cand) cand = t;
        }
        if (lane == k) wkey = cand;
        last = cand;
        if (cand == 0ull) break;
    }

    // recompute ciou for winners (<=10), reduce max_ovl, emit atomics
    float my_ciou = 0.0f, my_align = 0.0f;
    int my_a = -1;
    if (lane < KK && wkey != 0ull) {
        my_a = AA - (int)(unsigned int)(wkey & 0xffffffffull);
        my_align = __uint_as_float((unsigned int)(wkey >> 32));
        float4 gb = __ldg(((const float4*)gt_bboxes) + bg);
        float w1 = gb.z - gb.x, h1 = gb.w - gb.y;
        float at1 = atanf(__fdiv_rn(w1, h1 + FEPS));
        float4 d = ((const float4*)dbox)[(size_t)b * AA + my_a];
        float w2 = d.z - d.x, h2 = d.w - d.y;
        float at2 = atanf(__fdiv_rn(w2, h2 + FEPS));
        my_ciou = ciou_fn(gb.x, gb.y, gb.z, gb.w, w1 * h1, at1,
                          d.x, d.y, d.z, d.w, w2, h2, at2);
    }
    float max_ovl = my_ciou;
#pragma unroll
    for (int o = 16; o; o >>= 1)
        max_ovl = fmaxf(max_ovl, __shfl_xor_sync(0xffffffffu, max_ovl, o));

    unsigned long long w0 = __shfl_sync(0xffffffffu, wkey, 0);
    float max_align = __uint_as_float((unsigned int)(w0 >> 32));

    if (my_a >= 0) {
        float normv = __fdiv_rn(my_align * max_ovl, max_align + FEPS);
        unsigned long long akey =
            ((unsigned long long)__float_as_uint(my_ciou) << 32) |
            (unsigned int)(GG - 1 - g);  // smaller g wins ties
        atomicMax(&g_key[(size_t)b * AA + my_a], akey);
        atomicMax(&g_normb[(size_t)b * AA + my_a], __float_as_uint(normv));
    }
}

// ---------------------------------------------------------------------------
// fill: scatter-only, PER-BATCH 2D grid (33, B) so a block never straddles a
// batch boundary (the round-14 bug: flat blocks crossed batches while the
// smem gt tables were loaded for the first threads' batch). Gt tables
// prefetched to smem; per thread: one STG.128 bbox, one dist store, and a
// conditional one-hot STG.32 into the cls region already zeroed by scan.
// READ-ONLY on scratch. Output: bbox[B,A,4] | cls_oh[B,A,C] | dist | fg
// ---------------------------------------------------------------------------
__global__ __launch_bounds__(256) void fill_kernel(
    const int* __restrict__ gt_labels, const float* __restrict__ gt_bboxes,
    const float* __restrict__ gt_dist, float* __restrict__ out)
{
    __shared__ float4 s_gbox[GG];
    __shared__ float  s_gdist[GG];
    __shared__ int    s_glab[GG];

    int tid = threadIdx.x;
    int b = blockIdx.y;
    int a = blockIdx.x * 256 + tid;
    int w = b * AA + a;

    // independent streams: key/normb + gt-table prefetch (correct batch b)
    unsigned long long key = 0ull;
    unsigned int normb = 0u;
    if (a < AA) {
        key = __ldg(&g_key[w]);
        normb = __ldg(&g_normb[w]);
    }
    if (tid < GG) {
        int bg = b * GG + tid;
        s_gbox[tid]  = __ldg(((const float4*)gt_bboxes) + bg);
        s_gdist[tid] = __ldg(&gt_dist[bg]);
        s_glab[tid]  = __ldg(&gt_labels[bg]);
    }
    __syncthreads();
    if (a >= AA) return;

    float norm = __uint_as_float(normb);
    bool matched = (key != 0ull);
    int gm = (GG - 1) - ((int)key & (GG - 1));
    int label = matched ? s_glab[gm] : -1;

    float* out_dist = out + (size_t)BB * AA * (4 + CC);
    ((float4*)out)[w] = matched ? s_gbox[gm]
                                : make_float4(-1.f, -1.f, -1.f, -1.f);
    out_dist[w] = (matched ? s_gdist[gm] : -1.0f) * norm;

    if (label >= 0) {
        float* out_cls = out + (size_t)BB * AA * 4;
        out_cls[(size_t)w * CC + label] = norm;
    }
}

// ---------------------------------------------------------------------------
extern "C" void kernel_launch(void* const* d_in, const int* in_sizes, int n_in,
                              void* d_out, int out_size) {
    const float* scores = nullptr;
    const float* dbox = nullptr;
    const float* anchors = nullptr;
    const float* gtb = nullptr;
    const int* gtl = nullptr;
    const float* gtd = nullptr;
    const unsigned char* gmask = nullptr;
    int small_seen = 0;
    for (int i = 0; i < n_in; i++) {
        int s = in_sizes[i];
        if (s == BB * AA * CC)      scores = (const float*)d_in[i];
        else if (s == BB * AA * 4)  dbox = (const float*)d_in[i];
        else if (s == AA * 2)       anchors = (const float*)d_in[i];
        else if (s == BB * GG * 4)  gtb = (const float*)d_in[i];
        else if (s == BB * GG) {
            if (small_seen == 0)      gtl = (const int*)d_in[i];
            else if (small_seen == 1) gtd = (const float*)d_in[i];
            else                      gmask = (const unsigned char*)d_in[i];
            small_seen++;
        }
    }

    cellbin_kernel<<<BB * NCELL / 8, 256>>>(gtb, gmask);
    scan_kernel<<<dim3((AA + 255) / 256, BB), 256>>>(scores, dbox, anchors,
                                                     gtl, gtb, (float*)d_out);
    select_kernel<<<BB * GG / 2, 64>>>(dbox, gtb);
    fill_kernel<<<dim3((AA + 255) / 256, BB), 256>>>(gtl, gtb, gtd, (float*)d_out);
}